// round 12
// baseline (speedup 1.0000x reference)
#include <cuda_runtime.h>
#include <cuda_bf16.h>
#include <cstdint>

// Problem constants
#define Mv 8192
#define Nv 8192
#define Cv 80

#define ZSPLIT 16         // row interleave factor per class in write kernel
#define ROWS_T 64         // rows per vmat block
#define SPAD 81           // smem row stride -> conflict-free column walks

// Scratch (no allocation allowed in kernel_launch)
__device__ float g_V[Cv][Nv];     // V[c][n] = base[n] - pc[n][c]
__device__ int   g_perm[Mv];
__device__ int   g_off[Cv + 1];

// Fused phase 1: blocks 0..127 compute V; block 128 does the class grouping.
// blockDim = 256. Each block fires the PDL trigger after its global writes.
__global__ void __launch_bounds__(256) phase1_kernel(const float* __restrict__ pc,
                                                     const int* __restrict__ g) {
    if (blockIdx.x < 128) {
        // ---------------- vmat path: 64 rows, 4 threads per row ----------
        __shared__ float sp[ROWS_T * SPAD];       // 20.7 KB tile
        __shared__ float sS[ROWS_T][4];           // partial max-sums
        __shared__ float sP[ROWS_T][4];           // partial products
        __shared__ float sb[ROWS_T];              // base per row

        const int n0 = blockIdx.x * ROWS_T;
        const int t  = threadIdx.x;

        // Load tile (64 rows x 80 floats = 1280 float4), coalesced.
        const float4* src = reinterpret_cast<const float4*>(pc + (size_t)n0 * Cv);
#pragma unroll
        for (int i = 0; i < 5; i++) {
            int q4 = i * 256 + t;
            float4 v = src[q4];
            int row = q4 / 20, c4 = q4 % 20;
            float* d = &sp[row * SPAD + c4 * 4];
            d[0] = v.x; d[1] = v.y; d[2] = v.z; d[3] = v.w;
        }
        __syncthreads();

        // Each thread: 20 classes of one row. S = sum max(x,0); P = prod(1+e^{-|x|}).
        const int r = t & 63;
        const int q = t >> 6;
        float S = 0.0f, P = 1.0f;
#pragma unroll 5
        for (int j = 0; j < 20; j++) {
            float x = sp[r * SPAD + q * 20 + j];
            S += fmaxf(x, 0.0f);
            P *= 1.0f + __expf(-fabsf(x));
        }
        sS[r][q] = S;
        sP[r][q] = P;
        __syncthreads();

        // Rows reduce: base = sum(S) + log(prod(P))  -> one LG2 per row.
        if (t < ROWS_T) {
            float Ssum = sS[t][0] + sS[t][1] + sS[t][2] + sS[t][3];
            float Pprod = (sP[t][0] * sP[t][1]) * (sP[t][2] * sP[t][3]);
            sb[t] = Ssum + __logf(Pprod);
        }
        __syncthreads();

        // V[c][n0+r] = base[r] - x ; 64-float coalesced runs per c.
#pragma unroll 4
        for (int idx = t; idx < Cv * ROWS_T; idx += 256) {
            int c = idx >> 6, rr = idx & 63;
            g_V[c][n0 + rr] = sb[rr] - sp[rr * SPAD + c];
        }
        cudaTriggerProgrammaticLaunchCompletion();
    } else {
        // ---------------- group path: counting sort by class -------------
        __shared__ int cnt[Cv];     // counts (preserved)
        __shared__ int sc[Cv];      // inclusive scan
        __shared__ int cur[Cv];     // scatter cursors
        const int tid = threadIdx.x;
        if (tid < Cv) cnt[tid] = 0;
        __syncthreads();

        // Pass 1: histogram, int4 loads (2048 LDG.128 total).
        const int4* g4 = reinterpret_cast<const int4*>(g);
        for (int i = tid; i < Mv / 4; i += 256) {
            int4 v = g4[i];
            atomicAdd(&cnt[v.x], 1);
            atomicAdd(&cnt[v.y], 1);
            atomicAdd(&cnt[v.z], 1);
            atomicAdd(&cnt[v.w], 1);
        }
        __syncthreads();

        // Parallel inclusive scan (Hillis-Steele, 7 steps over 80 entries).
        if (tid < Cv) sc[tid] = cnt[tid];
        __syncthreads();
#pragma unroll
        for (int d = 1; d < Cv; d <<= 1) {
            int v = 0;
            if (tid < Cv && tid >= d) v = sc[tid - d];
            __syncthreads();
            if (tid < Cv) sc[tid] += v;
            __syncthreads();
        }
        if (tid == 0) g_off[0] = 0;
        if (tid < Cv) {
            g_off[tid + 1] = sc[tid];
            cur[tid] = sc[tid] - cnt[tid];   // exclusive offset = cursor start
        }
        __syncthreads();

        // Pass 2: scatter row indices, int4 loads.
        for (int i = tid; i < Mv / 4; i += 256) {
            int4 v = g4[i];
            int m = i * 4;
            g_perm[atomicAdd(&cur[v.x], 1)] = m;
            g_perm[atomicAdd(&cur[v.y], 1)] = m + 1;
            g_perm[atomicAdd(&cur[v.z], 1)] = m + 2;
            g_perm[atomicAdd(&cur[v.w], 1)] = m + 3;
        }
        cudaTriggerProgrammaticLaunchCompletion();
    }
}

// Write kernel: grid = (Nv/1024, Cv, ZSPLIT), block = 256. PDL secondary:
// waits for phase1's writes, then streams its V[c] slice to its interleaved
// subset of the class's output rows with evict-first stores.
__global__ void __launch_bounds__(256) write_kernel(float* __restrict__ out) {
    cudaGridDependencySynchronize();

    const int c  = blockIdx.y;
    const int z  = blockIdx.z;
    const int i0 = g_off[c];
    const int i1 = g_off[c + 1];
    if (i0 + z >= i1) return;

    const int n0 = (blockIdx.x * 256 + threadIdx.x) * 4;
    const float4 v = *reinterpret_cast<const float4*>(&g_V[c][n0]);

    float4* out4 = reinterpret_cast<float4*>(out);
    const size_t col = (size_t)(n0 >> 2);

    for (int i = i0 + z; i < i1; i += ZSPLIT) {
        int m = g_perm[i];                              // broadcast load
        __stcs(&out4[(size_t)m * (Nv / 4) + col], v);   // streaming STG.128
    }
}

extern "C" void kernel_launch(void* const* d_in, const int* in_sizes, int n_in,
                              void* d_out, int out_size) {
    const int*   g;
    const float* pc;
    if (in_sizes[0] == Mv) {
        g  = (const int*)d_in[0];
        pc = (const float*)d_in[1];
    } else {
        g  = (const int*)d_in[1];
        pc = (const float*)d_in[0];
    }
    float* out = (float*)d_out;

    phase1_kernel<<<129, 256>>>(pc, g);

    // PDL launch of the write kernel: may begin scheduling while phase1
    // drains; correctness guarded by cudaGridDependencySynchronize().
    cudaLaunchConfig_t cfg = {};
    cfg.gridDim  = dim3(Nv / 1024, Cv, ZSPLIT);
    cfg.blockDim = dim3(256, 1, 1);
    cfg.stream   = 0;
    cudaLaunchAttribute attr[1];
    attr[0].id = cudaLaunchAttributeProgrammaticStreamSerialization;
    attr[0].val.programmaticStreamSerializationAllowed = 1;
    cfg.attrs    = attr;
    cfg.numAttrs = 1;
    cudaLaunchKernelEx(&cfg, write_kernel, out);
}

// round 13
// speedup vs baseline: 1.1244x; 1.1244x over previous
#include <cuda_runtime.h>
#include <cuda_bf16.h>
#include <cstdint>

// Problem constants
#define Mv 8192
#define Nv 8192
#define Cv 80

#define ZSPLIT 16         // m-windows (512 rows each) in write kernel
#define MWIN   (Mv / ZSPLIT)   // 512
#define ROWS_T 64         // rows per vmat block
#define SPAD 81           // smem row stride -> conflict-free column walks

// Scratch (no allocation allowed in kernel_launch)
__device__ float g_V[Cv][Nv];     // V[c][n] = base[n] - pc[n][c]

// Phase 1: 128 blocks compute V (64 rows each). blockDim = 256.
// No grouping block anymore — write kernel self-selects rows via ballot scan.
__global__ void __launch_bounds__(256) phase1_kernel(const float* __restrict__ pc) {
    __shared__ float sp[ROWS_T * SPAD];       // 20.7 KB tile
    __shared__ float sS[ROWS_T][4];           // partial max-sums
    __shared__ float sP[ROWS_T][4];           // partial products
    __shared__ float sb[ROWS_T];              // base per row

    const int n0 = blockIdx.x * ROWS_T;
    const int t  = threadIdx.x;

    // Load tile (64 rows x 80 floats = 1280 float4), coalesced.
    const float4* src = reinterpret_cast<const float4*>(pc + (size_t)n0 * Cv);
#pragma unroll
    for (int i = 0; i < 5; i++) {
        int q4 = i * 256 + t;
        float4 v = src[q4];
        int row = q4 / 20, c4 = q4 % 20;
        float* d = &sp[row * SPAD + c4 * 4];
        d[0] = v.x; d[1] = v.y; d[2] = v.z; d[3] = v.w;
    }
    __syncthreads();

    // Each thread: 20 classes of one row. S = sum max(x,0); P = prod(1+e^{-|x|}).
    const int r = t & 63;
    const int q = t >> 6;
    float S = 0.0f, P = 1.0f;
#pragma unroll 5
    for (int j = 0; j < 20; j++) {
        float x = sp[r * SPAD + q * 20 + j];
        S += fmaxf(x, 0.0f);
        P *= 1.0f + __expf(-fabsf(x));
    }
    sS[r][q] = S;
    sP[r][q] = P;
    __syncthreads();

    // Rows reduce: base = sum(S) + log(prod(P)) -> one LG2 per row.
    if (t < ROWS_T) {
        float Ssum  = sS[t][0] + sS[t][1] + sS[t][2] + sS[t][3];
        float Pprod = (sP[t][0] * sP[t][1]) * (sP[t][2] * sP[t][3]);
        sb[t] = Ssum + __logf(Pprod);
    }
    __syncthreads();

    // V[c][n0+r] = base[r] - x ; 64-float coalesced runs per c.
#pragma unroll 4
    for (int idx = t; idx < Cv * ROWS_T; idx += 256) {
        int c = idx >> 6, rr = idx & 63;
        g_V[c][n0 + rr] = sb[rr] - sp[rr * SPAD + c];
    }
    cudaTriggerProgrammaticLaunchCompletion();
}

// Write kernel: grid = (Nv/1024, Cv, ZSPLIT), block = 256. PDL secondary.
// Block (x, c, z): scan g over m-window [z*512, z*512+512) with warp ballots
// to find rows of class c, then stream the 4KB V[c] column slice to each.
__global__ void __launch_bounds__(256) write_kernel(const int* __restrict__ g,
                                                    float* __restrict__ out) {
    __shared__ int rows[MWIN];
    __shared__ int cnt_s;

    cudaGridDependencySynchronize();

    const int c  = blockIdx.y;
    const int m0 = blockIdx.z * MWIN;
    const int t  = threadIdx.x;
    const int w  = t >> 5;      // warp 0..7
    const int l  = t & 31;

    if (t == 0) cnt_s = 0;
    __syncthreads();

    // Membership scan: each warp covers 64 m's (two 32-wide ballots).
#pragma unroll
    for (int half = 0; half < 2; half++) {
        int m = m0 + w * 64 + half * 32 + l;
        unsigned b = __ballot_sync(0xFFFFFFFFu, g[m] == c);
        int nmatch = __popc(b);
        int base = 0;
        if (l == 0 && nmatch) base = atomicAdd(&cnt_s, nmatch);
        base = __shfl_sync(0xFFFFFFFFu, base, 0);
        if (b & (1u << l)) {
            int pos = __popc(b & ((1u << l) - 1));
            rows[base + pos] = m;
        }
    }

    // V slice for this block's 1024 columns.
    const int n0 = blockIdx.x * 1024 + t * 4;
    const float4 v = *reinterpret_cast<const float4*>(&g_V[c][n0]);
    __syncthreads();

    const int nrows = cnt_s;
    float4* out4 = reinterpret_cast<float4*>(out);
    const size_t col = (size_t)(n0 >> 2);

    for (int k = 0; k < nrows; k++) {
        int m = rows[k];                                // LDS broadcast
        __stcs(&out4[(size_t)m * (Nv / 4) + col], v);   // streaming STG.128
    }
}

extern "C" void kernel_launch(void* const* d_in, const int* in_sizes, int n_in,
                              void* d_out, int out_size) {
    const int*   g;
    const float* pc;
    if (in_sizes[0] == Mv) {
        g  = (const int*)d_in[0];
        pc = (const float*)d_in[1];
    } else {
        g  = (const int*)d_in[1];
        pc = (const float*)d_in[0];
    }
    float* out = (float*)d_out;

    phase1_kernel<<<128, 256>>>(pc);

    // PDL launch of the write kernel: overlaps with phase1 drain;
    // correctness guarded by cudaGridDependencySynchronize().
    cudaLaunchConfig_t cfg = {};
    cfg.gridDim  = dim3(Nv / 1024, Cv, ZSPLIT);
    cfg.blockDim = dim3(256, 1, 1);
    cfg.stream   = 0;
    cudaLaunchAttribute attr[1];
    attr[0].id = cudaLaunchAttributeProgrammaticStreamSerialization;
    attr[0].val.programmaticStreamSerializationAllowed = 1;
    cfg.attrs    = attr;
    cfg.numAttrs = 1;
    cudaLaunchKernelEx(&cfg, write_kernel, g, out);
}

// round 14
// speedup vs baseline: 1.1352x; 1.0097x over previous
#include <cuda_runtime.h>
#include <cuda_bf16.h>
#include <cstdint>

// Problem constants
#define Mv 8192
#define Nv 8192
#define Cv 80

#define ZSPLIT 16         // m-windows (512 rows each) in write kernel
#define MWIN   (Mv / ZSPLIT)   // 512
#define ROWS_T 64         // rows per vmat block
#define SPAD 81           // smem row stride -> conflict-free column walks

// Scratch (no allocation allowed in kernel_launch)
__device__ float g_V[Cv][Nv];     // V[c][n] = base[n] - pc[n][c]

// Phase 1: 128 blocks compute V (64 rows each). blockDim = 256.
__global__ void __launch_bounds__(256) phase1_kernel(const float* __restrict__ pc) {
    __shared__ float sp[ROWS_T * SPAD];       // 20.7 KB tile
    __shared__ float sS[ROWS_T][4];           // partial max-sums
    __shared__ float sP[ROWS_T][4];           // partial products
    __shared__ float sb[ROWS_T];              // base per row

    const int n0 = blockIdx.x * ROWS_T;
    const int t  = threadIdx.x;

    // Load tile (64 rows x 80 floats = 1280 float4), coalesced.
    const float4* src = reinterpret_cast<const float4*>(pc + (size_t)n0 * Cv);
#pragma unroll
    for (int i = 0; i < 5; i++) {
        int q4 = i * 256 + t;
        float4 v = src[q4];
        int row = q4 / 20, c4 = q4 % 20;
        float* d = &sp[row * SPAD + c4 * 4];
        d[0] = v.x; d[1] = v.y; d[2] = v.z; d[3] = v.w;
    }
    __syncthreads();

    // Each thread: 20 classes of one row. S = sum max(x,0); P = prod(1+e^{-|x|}).
    const int r = t & 63;
    const int q = t >> 6;
    float S = 0.0f, P = 1.0f;
#pragma unroll 5
    for (int j = 0; j < 20; j++) {
        float x = sp[r * SPAD + q * 20 + j];
        S += fmaxf(x, 0.0f);
        P *= 1.0f + __expf(-fabsf(x));
    }
    sS[r][q] = S;
    sP[r][q] = P;
    __syncthreads();

    // Rows reduce: base = sum(S) + log(prod(P)) -> one LG2 per row.
    if (t < ROWS_T) {
        float Ssum  = sS[t][0] + sS[t][1] + sS[t][2] + sS[t][3];
        float Pprod = (sP[t][0] * sP[t][1]) * (sP[t][2] * sP[t][3]);
        sb[t] = Ssum + __logf(Pprod);
    }
    __syncthreads();

    // V[c][n0+r] = base[r] - x ; 64-float coalesced runs per c.
#pragma unroll 4
    for (int idx = t; idx < Cv * ROWS_T; idx += 256) {
        int c = idx >> 6, rr = idx & 63;
        g_V[c][n0 + rr] = sb[rr] - sp[rr * SPAD + c];
    }
    cudaTriggerProgrammaticLaunchCompletion();
}

// Write kernel: grid = (Nv/1024, Cv, ZSPLIT), block = 256. PDL secondary.
// Preamble (before grid-dependency sync): ballot membership scan of the
// INPUT array g — overlaps with phase1's drain. Then sync, load the V[c]
// slice, and stream it to the matched rows with evict-first stores.
__global__ void __launch_bounds__(256) write_kernel(const int* __restrict__ g,
                                                    float* __restrict__ out) {
    __shared__ int rows[MWIN];
    __shared__ int cnt_s;

    const int c  = blockIdx.y;
    const int m0 = blockIdx.z * MWIN;
    const int t  = threadIdx.x;
    const int w  = t >> 5;      // warp 0..7
    const int l  = t & 31;

    if (t == 0) cnt_s = 0;
    __syncthreads();

    // Membership scan over input g (independent of phase1's output).
#pragma unroll
    for (int half = 0; half < 2; half++) {
        int m = m0 + w * 64 + half * 32 + l;
        unsigned b = __ballot_sync(0xFFFFFFFFu, g[m] == c);
        int nmatch = __popc(b);
        int base = 0;
        if (l == 0 && nmatch) base = atomicAdd(&cnt_s, nmatch);
        base = __shfl_sync(0xFFFFFFFFu, base, 0);
        if (b & (1u << l)) {
            int pos = __popc(b & ((1u << l) - 1));
            rows[base + pos] = m;
        }
    }
    __syncthreads();

    // Now wait for phase1's V writes, then read our slice.
    cudaGridDependencySynchronize();

    const int n0 = blockIdx.x * 1024 + t * 4;
    const float4 v = *reinterpret_cast<const float4*>(&g_V[c][n0]);

    const int nrows = cnt_s;
    float4* out4 = reinterpret_cast<float4*>(out);
    const size_t col = (size_t)(n0 >> 2);

    for (int k = 0; k < nrows; k++) {
        int m = rows[k];                                // LDS broadcast
        __stcs(&out4[(size_t)m * (Nv / 4) + col], v);   // streaming STG.128
    }
}

extern "C" void kernel_launch(void* const* d_in, const int* in_sizes, int n_in,
                              void* d_out, int out_size) {
    const int*   g;
    const float* pc;
    if (in_sizes[0] == Mv) {
        g  = (const int*)d_in[0];
        pc = (const float*)d_in[1];
    } else {
        g  = (const int*)d_in[1];
        pc = (const float*)d_in[0];
    }
    float* out = (float*)d_out;

    phase1_kernel<<<128, 256>>>(pc);

    // PDL launch of the write kernel: preamble overlaps with phase1 drain;
    // correctness guarded by cudaGridDependencySynchronize().
    cudaLaunchConfig_t cfg = {};
    cfg.gridDim  = dim3(Nv / 1024, Cv, ZSPLIT);
    cfg.blockDim = dim3(256, 1, 1);
    cfg.stream   = 0;
    cudaLaunchAttribute attr[1];
    attr[0].id = cudaLaunchAttributeProgrammaticStreamSerialization;
    attr[0].val.programmaticStreamSerializationAllowed = 1;
    cfg.attrs    = attr;
    cfg.numAttrs = 1;
    cudaLaunchKernelEx(&cfg, write_kernel, g, out);
}